// round 16
// baseline (speedup 1.0000x reference)
#include <cuda_runtime.h>
#include <stdint.h>

#define NN     4096
#define NE     8192
#define TOT    (1u << 26)     // E*E
#define KEEP   16384          // K*E
#define NBUCK  16384          // buckets on t>>12 (4096 t-values each, lambda~1)
#define SLOTS  16

#define SCAN_BLOCKS 1184              // 148 SMs x 8 resident blocks: ONE wave
#define STRIDE      (SCAN_BLOCKS * 256)
// 221*STRIDE = 66,985,984 ; remainder 122,880 = 480 blocks * 256 -> blocks<480 do one extra iter

// ---- device scratch (no allocations allowed) ----
__device__ uint32_t g_adj[(NN * NN) / 32];    // 2MB adjacency bitmap
__device__ uint32_t g_claim[(NN * NN) / 32];  // 2MB dedup-claim bitmap
__device__ int      g_cnt_src[NN];
__device__ int      g_cnt_dst[NN];
__device__ int      g_inv[NN];
__device__ int      g_num_neg;
__device__ unsigned g_hist[NBUCK];
__device__ uint32_t g_bucket[NBUCK * SLOTS];

// ---------------- zero scratch ----------------
__global__ void k_zero() {
    unsigned i = blockIdx.x * blockDim.x + threadIdx.x;
    unsigned stride = gridDim.x * blockDim.x;
    for (unsigned w = i; w < (NN * NN) / 32; w += stride) { g_adj[w] = 0u; g_claim[w] = 0u; }
    for (unsigned w = i; w < NBUCK; w += stride) g_hist[w] = 0u;
    if (i < NN) { g_cnt_src[i] = 0; g_cnt_dst[i] = 0; g_inv[i] = 0; }
    if (i == 0) g_num_neg = 0;
}

// ---------------- fused build + inv + num_neg (single block, 1024 thr) ----------------
// inv[v] = sum over DISTINCT (n,v) in adj, n!=v, of cnt_src[n]
// num_neg = sum_v cnt_dst[v] * (E - cnt_src[v] - inv[v])
__global__ void k_prep(const int* __restrict__ src, const int* __restrict__ dst) {
    int tid = threadIdx.x;
    // phase 1: histograms + adjacency bitmap
    for (int e = tid; e < NE; e += 1024) {
        int n = src[e] & (NN - 1), v = dst[e] & (NN - 1);
        unsigned idx = ((unsigned)n << 12) | (unsigned)v;
        atomicOr(&g_adj[idx >> 5], 1u << (idx & 31));
        atomicAdd(&g_cnt_src[n], 1);
        atomicAdd(&g_cnt_dst[v], 1);
    }
    __syncthreads();
    // phase 2: dedup pairs via claim bitmap, accumulate inv[v]
    for (int e = tid; e < NE; e += 1024) {
        int n = src[e] & (NN - 1), v = dst[e] & (NN - 1);
        unsigned idx = ((unsigned)n << 12) | (unsigned)v;
        unsigned bit = 1u << (idx & 31);
        unsigned old = atomicOr(&g_claim[idx >> 5], bit);
        if (!(old & bit) && n != v) atomicAdd(&g_inv[v], g_cnt_src[n]);
    }
    __syncthreads();
    // phase 3: num_neg reduction
    int s = 0;
    for (int v = tid; v < NN; v += 1024)
        s += g_cnt_dst[v] * (NE - g_cnt_src[v] - g_inv[v]);
    #pragma unroll
    for (int o = 16; o > 0; o >>= 1) s += __shfl_down_sync(0xFFFFFFFFu, s, o);
    if ((tid & 31) == 0) atomicAdd(&g_num_neg, s);
}

// ---------------- threefry2x32 — partitionable scheme (verified bit-exact R14) -------
// key = (0, 42); ks0=0, ks1=42, ks2 = 0^42^0x1BD11BDA = 0x1BD11BF0
// element t: (x0 = hi = 0, x1 = lo = t); bits[t] = o0 ^ o1
// Adds routed to the FMA pipe via IMAD (alu pipe is the binding floor: SHF+LOP3).
__device__ __forceinline__ uint32_t addm(uint32_t a, uint32_t b, uint32_t one) {
    uint32_t d;
    asm("mad.lo.u32 %0, %1, %2, %3;" : "=r"(d) : "r"(a), "r"(one), "r"(b));
    return d;
}
#define ROTX(r) { x1 = __funnelshift_l(x1, x1, (r)); x1 ^= x0; }
#define TFR(r)  { x0 = addm(x0, x1, one); ROTX(r) }

__device__ __forceinline__ uint32_t tf_bits(uint32_t t, uint32_t one) {
    uint32_t x1 = addm(t, 42u, one);    // lo + ks1
    uint32_t x0 = x1;                   // round 1: x0(=0) += x1
    ROTX(13) TFR(15) TFR(26) TFR(6)
    x0 = addm(x0, 42u, one);          x1 = addm(x1, 0x1BD11BF1u, one);  // ks1 ; ks2+1
    TFR(17) TFR(29) TFR(16) TFR(24)
    x0 = addm(x0, 0x1BD11BF0u, one);  x1 = addm(x1, 2u, one);           // ks2 ; ks0+2
    TFR(13) TFR(15) TFR(26) TFR(6)
                                      x1 = addm(x1, 45u, one);          // ks0 ; ks1+3
    TFR(17) TFR(29) TFR(16) TFR(24)
    x0 = addm(x0, 42u, one);          x1 = addm(x1, 0x1BD11BF4u, one);  // ks1 ; ks2+4
    TFR(13) TFR(15) TFR(26) TFR(6)
    x0 = addm(x0, 0x1BD11BF0u, one);  x1 = addm(x1, 5u, one);           // ks2 ; ks0+5
    return x0 ^ x1;
}

__device__ __forceinline__ void try_keep(uint32_t t,
                                         const int* __restrict__ src,
                                         const int* __restrict__ dst) {
    int n = __ldg(&src[t >> 13]);
    int v = __ldg(&dst[t & 8191u]);
    if (n != v) {
        uint32_t w = g_adj[(((unsigned)n << 12) | (unsigned)v) >> 5];
        if (!((w >> (v & 31)) & 1u)) {
            unsigned b = t >> 12;
            unsigned p = atomicAdd(&g_hist[b], 1u);
            if (p < SLOTS) g_bucket[b * SLOTS + p] = t;
        }
    }
}

__global__ void __launch_bounds__(256) k_scan(const int* __restrict__ src,
                                              const int* __restrict__ dst,
                                              uint32_t one) {
    // keep_prob = fl32(2/(num_neg//E)); u < kp  <=>  bits < ceil(kp*2^23) << 9
    int ratio = g_num_neg >> 13;
    float kp = __fdiv_rn(2.0f, (float)ratio);
    uint32_t th = ((uint32_t)ceilf(kp * 8388608.0f)) << 9;

    uint32_t t = blockIdx.x * 256u + threadIdx.x;
    // 55 groups of 4 = 220 iterations; branch/reconvergence cost amortized 4x
    for (int g = 0; g < 55; g++) {
        uint32_t t0 = t, t1 = t + STRIDE, t2 = t + 2u * STRIDE, t3 = t + 3u * STRIDE;
        uint32_t b0 = tf_bits(t0, one);
        uint32_t b1 = tf_bits(t1, one);
        uint32_t b2 = tf_bits(t2, one);
        uint32_t b3 = tf_bits(t3, one);
        if ((b0 < th) | (b1 < th) | (b2 < th) | (b3 < th)) {
            if (b0 < th) try_keep(t0, src, dst);
            if (b1 < th) try_keep(t1, src, dst);
            if (b2 < th) try_keep(t2, src, dst);
            if (b3 < th) try_keep(t3, src, dst);
        }
        t += 4u * STRIDE;
    }
    // tail: iter 220 (all blocks), iter 221 (blocks < 480) -> exactly 2^26 covered
    if (tf_bits(t, one) < th) try_keep(t, src, dst);
    if (blockIdx.x < 480u) {
        t += STRIDE;
        if (tf_bits(t, one) < th) try_keep(t, src, dst);
    }
}

// ---------------- fused fill + prefix + place (single block, 1024 thr) ----------------
__global__ void k_final(const int* __restrict__ src, const int* __restrict__ dst,
                        float* __restrict__ out) {
    __shared__ unsigned sh[1024];
    unsigned i = threadIdx.x;

    // phase A: pad defaults (fill_value=0 -> flat idx 0 -> src[0], dst[0])
    float s0 = (float)src[0], d0 = (float)dst[0];
    for (unsigned k = i; k < KEEP; k += 1024u) { out[k] = s0; out[KEEP + k] = d0; }

    // phase B: load counts (clamped), block exclusive scan over 16384 buckets
    unsigned loc[16], s = 0;
    #pragma unroll
    for (int j = 0; j < 16; j++) { loc[j] = min(g_hist[i * 16 + j], (unsigned)SLOTS); s += loc[j]; }
    sh[i] = s; __syncthreads();
    for (int d = 1; d < 1024; d <<= 1) {
        unsigned v = (i >= (unsigned)d) ? sh[i - d] : 0u;
        __syncthreads();
        sh[i] += v;
        __syncthreads();
    }
    unsigned run = (i > 0) ? sh[i - 1] : 0u;

    // phase C: per-bucket tiny sort + emit at global rank (overwrites defaults)
    #pragma unroll 1
    for (int j = 0; j < 16; j++) {
        unsigned b = i * 16 + j;
        unsigned c = loc[j];
        uint32_t v[SLOTS];
        for (unsigned q = 0; q < c; q++) v[q] = g_bucket[b * SLOTS + q];
        for (unsigned q = 1; q < c; q++) {            // insertion sort (c ~ 0-3)
            uint32_t x = v[q]; int p = (int)q - 1;
            while (p >= 0 && v[p] > x) { v[p + 1] = v[p]; p--; }
            v[p + 1] = x;
        }
        for (unsigned q = 0; q < c; q++) {
            unsigned r = run + q;
            if (r < KEEP) {
                uint32_t t = v[q];
                out[r]        = (float)__ldg(&src[t >> 13]);
                out[KEEP + r] = (float)__ldg(&dst[t & 8191u]);
            }
        }
        run += c;
    }
}

extern "C" void kernel_launch(void* const* d_in, const int* in_sizes, int n_in,
                              void* d_out, int out_size) {
    // edge_src is index 1 under both dict and alphabetical ordering;
    // node_feature is the unique 262144-element input; edge_dst is the rest.
    int feat_idx = 0;
    for (int i = 0; i < n_in; i++)
        if (in_sizes[i] == NN * 64) feat_idx = i;
    int dst_idx = -1;
    for (int i = 0; i < n_in; i++)
        if (i != feat_idx && i != 1) { dst_idx = i; break; }
    if (dst_idx < 0) dst_idx = 2;

    const int* src = (const int*)d_in[1];
    const int* dst = (const int*)d_in[dst_idx];
    float* out = (float*)d_out;

    k_zero  <<<1024, 256>>>();
    k_prep  <<<1, 1024>>>(src, dst);
    k_scan  <<<SCAN_BLOCKS, 256>>>(src, dst, 1u);
    k_final <<<1, 1024>>>(src, dst, out);
}